// round 15
// baseline (speedup 1.0000x reference)
#include <cuda_runtime.h>
#include <cuda_fp16.h>
#include <cstdint>

#define NPTS 8192
#define DIM 128
#define SSTRIDE 272                   // f16 tile row stride bytes (136 halves)
#define TILE_BYTES (128 * SSTRIDE)    // 34816

// packed half2 constants: C = 2*log2(e) rounded to f16 = 2.884765625 (0x41C5)
#define SCALE2 0x41C541C5u            // ( C,  C)
#define BIAS2  0xC1C5C1C5u            // (-C, -C)

// ---------------- scratch (device globals; no allocations allowed) ----------
__device__ __half g_src[NPTS * DIM];
__device__ __half g_pos[NPTS * DIM];
__device__ float g_dot[NPTS];
__device__ float g_rowsum[2 * 2 * NPTS];            // [my][z][bi][row]
__device__ float g_cross[2 * 64 * 33 * 2 * 128];    // [my][bj][t][warp_m][row]
__device__ float g_lse_partial[128];                // [my(2)][row-block(64)]
__device__ float g_dotp[64];
__device__ int   g_ready[64];                       // per row-block gather counter (target 4)
__device__ int   g_done;                            // lse completion counter (reset election)
__device__ int   g_count;                           // reduce last-block election counter

// ---------------- PTX helpers ------------------------------------------------
__device__ __forceinline__ uint32_t smem_u32(const void* p) {
    uint32_t a;
    asm("{ .reg .u64 t; cvta.to.shared.u64 t, %1; cvt.u32.u64 %0, t; }"
        : "=r"(a) : "l"(p));
    return a;
}

__device__ __forceinline__ int ld_acquire(const int* p) {
    int v;
    asm volatile("ld.acquire.gpu.global.s32 %0, [%1];" : "=r"(v) : "l"(p));
    return v;
}

__device__ __forceinline__ uint32_t ex2h2(uint32_t a) {
    uint32_t d;
    asm("ex2.approx.f16x2 %0, %1;" : "=r"(d) : "r"(a));
    return d;
}
__device__ __forceinline__ uint32_t hadd2u(uint32_t a, uint32_t b) {
    uint32_t d;
    asm("add.f16x2 %0, %1, %2;" : "=r"(d) : "r"(a), "r"(b));
    return d;
}
__device__ __forceinline__ uint32_t hmul2u(uint32_t a, uint32_t b) {
    uint32_t d;
    asm("mul.f16x2 %0, %1, %2;" : "=r"(d) : "r"(a), "r"(b));
    return d;
}

#define CP_ASYNC16(dst, src) \
    asm volatile("cp.async.cg.shared.global [%0], [%1], 16;" :: "r"(dst), "l"(src) : "memory")
#define CP_COMMIT() asm volatile("cp.async.commit_group;" ::: "memory")
#define CP_WAIT2()  asm volatile("cp.async.wait_group 2;" ::: "memory")
#define CP_WAIT1()  asm volatile("cp.async.wait_group 1;" ::: "memory")
#define CP_WAIT0()  asm volatile("cp.async.wait_group 0;" ::: "memory")

#define LDMATRIX_X4(r0, r1, r2, r3, addr) \
    asm volatile("ldmatrix.sync.aligned.m8n8.x4.shared.b16 {%0,%1,%2,%3}, [%4];" \
                 : "=r"(r0), "=r"(r1), "=r"(r2), "=r"(r3) : "r"(addr))
#define LDMATRIX_X2(r0, r1, addr) \
    asm volatile("ldmatrix.sync.aligned.m8n8.x2.shared.b16 {%0,%1}, [%2];" \
                 : "=r"(r0), "=r"(r1) : "r"(addr))

// f16 x f16 -> f16 accumulate: D/C are 2 x .f16x2 registers.
#define MMA16816H(c0, c1, a0, a1, a2, a3, b0, b1) \
    asm volatile("mma.sync.aligned.m16n8k16.row.col.f16.f16.f16.f16 " \
                 "{%0,%1}, {%2,%3,%4,%5}, {%6,%7}, {%0,%1};" \
                 : "+r"(c0), "+r"(c1) \
                 : "r"(a0), "r"(a1), "r"(a2), "r"(a3), "r"(b0), "r"(b1))

// ---------------- fused gather + HMMA-f16 Gram + exp sums --------------------
// grid (64, 2, 2): x = row-block bi, y = matrix, z = t-range half.
// Phase 1: CTA (bi,my,zz) gathers rows bi*128 + (my*2+zz)*32 + [0,32)
//   (u AND v: normalize, f16 store, align dot). The 4 CTAs sharing bi jointly
//   produce row-block bi; readiness flagged via g_ready[bi] (target 4).
// Phase 2: tournament tiles (bi, (bi+t)%64), t in z's half of [0,NT),
//   NT=32(+1 if bi<32); every tile load waits on its block's g_ready.
// All 256 CTAs are wave-1 resident (2 CTAs/SM via launch_bounds+smem) so the
// producer/consumer flags cannot deadlock.
#define SM_A  0
#define SM_B0 TILE_BYTES
#define SM_B1 (2 * TILE_BYTES)
#define SM_TOTAL (3 * TILE_BYTES)

__device__ __forceinline__ void load_tile(uint32_t sdst, const uint4* eg,
                                          int row0, int tid) {
    #pragma unroll
    for (int it = 0; it < 8; it++) {
        int idx = tid + it * 256;
        int r = idx >> 4, c = idx & 15;
        CP_ASYNC16(sdst + r * SSTRIDE + c * 16, eg + (row0 + r) * 16 + c);
    }
}

__device__ __forceinline__ void wait_block(int b, int tid) {
    if (tid == 0) {
        while (ld_acquire(&g_ready[b]) < 4) { }
    }
    __syncthreads();
}

__global__ void __launch_bounds__(256, 2) lse_kernel(
        const void* __restrict__ u_raw, const void* __restrict__ v_raw,
        const float* __restrict__ emb) {
    extern __shared__ char smem[];
    const uint32_t sbase = smem_u32(smem);
    const int tid = threadIdx.x;
    const int lane = tid & 31;
    const int warp = tid >> 5;            // 0..7
    const int warp_m = warp >> 2;         // 0..1 -> 64 rows each
    const int warp_n = warp & 3;          // 0..3 -> 32 cols each
    const int m_base = warp_m * 64;
    const int n_base = warp_n * 32;
    const int bi = blockIdx.x;
    const int my = blockIdx.y;
    const int zz = blockIdx.z;
    const int NT = 32 + (bi < 32 ? 1 : 0);
    const int t0 = zz * 16;
    const int tEnd = zz == 0 ? 16 : NT;

    // ---------------- phase 1: gather 32 rows (both matrices) ----------------
    {
        const int* u32 = (const int*)u_raw;
        int nz = u32[2 * lane + 1];
        #pragma unroll
        for (int off = 16; off; off >>= 1)
            nz |= __shfl_xor_sync(0xffffffffu, nz, off);
        const bool is64 = (nz == 0);

        const int rbase = bi * 128 + (my * 2 + zz) * 32;
        #pragma unroll
        for (int it = 0; it < 4; it++) {
            int row = rbase + it * 8 + warp;

            long long ui, vi;
            if (is64) {
                ui = ((const long long*)u_raw)[row];
                vi = ((const long long*)v_raw)[row];
            } else {
                ui = ((const int*)u_raw)[row];
                vi = ((const int*)v_raw)[row];
            }

            float4 xu = ((const float4*)(emb + ui * DIM))[lane];
            float4 xv = ((const float4*)(emb + vi * DIM))[lane];

            float su2 = xu.x * xu.x + xu.y * xu.y + xu.z * xu.z + xu.w * xu.w;
            float sv2 = xv.x * xv.x + xv.y * xv.y + xv.z * xv.z + xv.w * xv.w;
            #pragma unroll
            for (int off = 16; off; off >>= 1) {
                su2 += __shfl_xor_sync(0xffffffffu, su2, off);
                sv2 += __shfl_xor_sync(0xffffffffu, sv2, off);
            }

            float ru = 1.0f / fmaxf(sqrtf(su2), 1e-12f);
            float rv = 1.0f / fmaxf(sqrtf(sv2), 1e-12f);
            float sux = xu.x * ru, suy = xu.y * ru, suz = xu.z * ru, suw = xu.w * ru;
            float svx = xv.x * rv, svy = xv.y * rv, svz = xv.z * rv, svw = xv.w * rv;

            __half2 u01 = __floats2half2_rn(sux, suy);
            __half2 u23 = __floats2half2_rn(suz, suw);
            __half2 v01 = __floats2half2_rn(svx, svy);
            __half2 v23 = __floats2half2_rn(svz, svw);
            *(uint2*)&g_src[row * DIM + lane * 4] =
                make_uint2(*(uint32_t*)&u01, *(uint32_t*)&u23);
            *(uint2*)&g_pos[row * DIM + lane * 4] =
                make_uint2(*(uint32_t*)&v01, *(uint32_t*)&v23);

            float dp = sux * svx + suy * svy + suz * svz + suw * svw;
            #pragma unroll
            for (int off = 16; off; off >>= 1)
                dp += __shfl_xor_sync(0xffffffffu, dp, off);
            if (lane == 0) g_dot[row] = dp;
        }
        __threadfence();                   // publish rows before flagging
        __syncthreads();
        if (tid == 0) atomicAdd(&g_ready[bi], 1);
    }

    // ---------------- phase 2: tournament MMA + exp sums ----------------
    const __half* e = (my == 0) ? g_src : g_pos;
    const uint4* eg = (const uint4*)e;

    // prologue: A alone in group0, B(t0) group1, B(t0+1) group2
    wait_block(bi, tid);
    load_tile(sbase + SM_A, eg, bi * 128, tid);
    CP_COMMIT();
    wait_block((bi + t0) & 63, tid);
    load_tile(sbase + SM_B0, eg, ((bi + t0) & 63) * 128, tid);
    CP_COMMIT();
    wait_block((bi + t0 + 1) & 63, tid);
    load_tile(sbase + SM_B1, eg, ((bi + t0 + 1) & 63) * 128, tid);
    CP_COMMIT();

    // A landed -> scale it by C in place (pad bytes scaled too: never read)
    CP_WAIT2();
    {
        uint32_t* aw = (uint32_t*)smem;
        #pragma unroll
        for (int i = tid; i < TILE_BYTES / 4; i += 256)
            aw[i] = hmul2u(aw[i], SCALE2);
    }

    const int l15 = lane & 15;
    const uint32_t aAddr0 = sbase + SM_A +
        (uint32_t)(m_base + l15) * SSTRIDE + (uint32_t)(lane >> 4) * 16;
    const uint32_t bOff0 =
        (uint32_t)(n_base + (l15 & 7)) * SSTRIDE + (uint32_t)(l15 >> 3) * 16;

    uint32_t acc[4][4][2];                // f16x2 accumulators, bias-initialized
    #pragma unroll
    for (int mt = 0; mt < 4; mt++)
        #pragma unroll
        for (int nt = 0; nt < 4; nt++) { acc[mt][nt][0] = BIAS2; acc[mt][nt][1] = BIAS2; }

    float rowsum[8];
    #pragma unroll
    for (int j = 0; j < 8; j++) rowsum[j] = 0.f;

    for (int t = t0; t < tEnd; t++) {
        if (t < tEnd - 1) { CP_WAIT1(); } else { CP_WAIT0(); }
        __syncthreads();                  // covers A-scale stores + B_t arrival

        const uint32_t bAddr0 = sbase + ((t & 1) ? SM_B1 : SM_B0) + bOff0;

        #pragma unroll
        for (int k = 0; k < 8; k++) {
            uint32_t b[4][2];
            #pragma unroll
            for (int nt = 0; nt < 4; nt++)
                LDMATRIX_X2(b[nt][0], b[nt][1],
                            bAddr0 + nt * (8 * SSTRIDE) + k * 32);
            #pragma unroll
            for (int mt = 0; mt < 4; mt++) {
                uint32_t a0, a1, a2, a3;
                LDMATRIX_X4(a0, a1, a2, a3,
                            aAddr0 + mt * (16 * SSTRIDE) + k * 32);
                #pragma unroll
                for (int nt = 0; nt < 4; nt++)
                    MMA16816H(acc[mt][nt][0], acc[mt][nt][1],
                              a0, a1, a2, a3, b[nt][0], b[nt][1]);
            }
        }

        __syncthreads();            // all warps done reading this B buffer
        if (t + 2 < tEnd) {
            wait_block((bi + t + 2) & 63, tid);
            load_tile(sbase + ((t & 1) ? SM_B1 : SM_B0), eg,
                      ((bi + t + 2) & 63) * 128, tid);
            CP_COMMIT();
        }

        // epilogue: acc already = C*d - C; ev = ex2(acc)
        uint32_t cs2[4];
        #pragma unroll
        for (int nt = 0; nt < 4; nt++) cs2[nt] = 0u;

        #pragma unroll
        for (int mt = 0; mt < 4; mt++) {
            uint32_t sr01 = 0u, sr23 = 0u;      // half2 row partials
            #pragma unroll
            for (int nt = 0; nt < 4; nt++) {
                uint32_t h01 = ex2h2(acc[mt][nt][0]);   // row r  : cols c,c+1
                uint32_t h23 = ex2h2(acc[mt][nt][1]);   // row r+8: cols c,c+1
                sr01 = hadd2u(sr01, h01);
                sr23 = hadd2u(sr23, h23);
                cs2[nt] = hadd2u(cs2[nt], hadd2u(h01, h23));
                acc[mt][nt][0] = BIAS2; acc[mt][nt][1] = BIAS2;
            }
            float2 fr01 = __half22float2(*(__half2*)&sr01);
            float2 fr23 = __half22float2(*(__half2*)&sr23);
            rowsum[mt * 2]     += fr01.x + fr01.y;
            rowsum[mt * 2 + 1] += fr23.x + fr23.y;
        }

        if (t != 0) {
            // col sums: xor-reduce half2 over the 8 row-groups, store f32
            #pragma unroll
            for (int nt = 0; nt < 4; nt++) {
                uint32_t c = cs2[nt];
                c = hadd2u(c, __shfl_xor_sync(0xffffffffu, c, 4));
                c = hadd2u(c, __shfl_xor_sync(0xffffffffu, c, 8));
                c = hadd2u(c, __shfl_xor_sync(0xffffffffu, c, 16));
                cs2[nt] = c;
            }
            if (lane < 4) {
                int bj = (bi + t) & 63;
                float2* dst = (float2*)&g_cross[
                    ((((my * 64 + bj) * 33 + t) * 2 + warp_m) * 128)
                    + n_base + lane * 2];
                #pragma unroll
                for (int nt = 0; nt < 4; nt++) {
                    float2 f = __half22float2(*(__half2*)&cs2[nt]);
                    dst[nt * 4] = f;
                }
            }
        }
    }

    // ---- own row sums: quad lanes share rows ----
    #pragma unroll
    for (int j = 0; j < 8; j++) {
        rowsum[j] += __shfl_xor_sync(0xffffffffu, rowsum[j], 1);
        rowsum[j] += __shfl_xor_sync(0xffffffffu, rowsum[j], 2);
    }

    float* red = (float*)smem;            // reuse A region
    __syncthreads();
    if ((lane & 3) == 0) {
        #pragma unroll
        for (int mt = 0; mt < 4; mt++) {
            int row = m_base + mt * 16 + (lane >> 2);
            red[warp_n * 128 + row]     = rowsum[mt * 2];
            red[warp_n * 128 + row + 8] = rowsum[mt * 2 + 1];
        }
    }
    __syncthreads();
    if (tid < 128) {
        float s = red[tid] + red[128 + tid] + red[256 + tid] + red[384 + tid];
        g_rowsum[((my * 2 + zz) * 64 + bi) * 128 + tid] = s;
    }

    // ---- replay-safe flag reset: last CTA of this launch zeroes g_ready ----
    __syncthreads();
    if (tid == 0) {
        __threadfence();
        int old = atomicAdd(&g_done, 1);
        if ((old & 255) == 255) {
            #pragma unroll
            for (int i = 0; i < 64; i++) g_ready[i] = 0;
            __threadfence();
        }
    }
}

// ------- per-row combine + log + block partial + fenced last-block finalize --
__global__ void __launch_bounds__(1024) reduce_kernel(float* __restrict__ out) {
    const int bi = blockIdx.x;
    const int my = blockIdx.y;
    const int tid = threadIdx.x;         // 0..1023
    const int r = tid & 127;
    const int q = tid >> 7;              // segment 0..7

    const float* cr = &g_cross[(my * 64 + bi) * 33 * 2 * 128 + r];
    float s = 0.f;
    if (q == 0) {
        s += g_rowsum[((my * 2 + 0) * 64 + bi) * 128 + r];
        s += g_rowsum[((my * 2 + 1) * 64 + bi) * 128 + r];
        #pragma unroll
        for (int t = 1; t <= 4; t++)  s += cr[t * 256] + cr[t * 256 + 128];
    } else if (q < 7) {
        const int tb = q * 4;            // q=1 -> 5..8, ..., q=6 -> 25..28
        #pragma unroll
        for (int t = 1; t <= 4; t++)
            s += cr[(tb + t) * 256] + cr[(tb + t) * 256 + 128];
    } else {
        const int tMax = (bi >= 32) ? 32 : 31;
        for (int t = 29; t <= tMax; t++) s += cr[t * 256] + cr[t * 256 + 128];
    }

    __shared__ float sm2[1024];
    sm2[tid] = s;
    __syncthreads();
    if (q == 0) {
        float v = sm2[r];
        #pragma unroll
        for (int j = 1; j < 8; j++) v += sm2[r + 128 * j];
        sm2[r] = logf(v);
    }
    __syncthreads();
    for (int st = 64; st; st >>= 1) {
        if (tid < st) sm2[tid] += sm2[tid + st];
        __syncthreads();
    }
    if (tid == 0) g_lse_partial[my * 64 + bi] = sm2[0];

    if (my == 0) {
        sm2[tid] = (tid < 128) ? g_dot[bi * 128 + tid] : 0.f;
        __syncthreads();
        for (int st = 64; st; st >>= 1) {
            if (tid < st) sm2[tid] += sm2[tid + st];
            __syncthreads();
        }
        if (tid == 0) g_dotp[bi] = sm2[0];
    }

    // ---- last-of-128-blocks finalize (threadfence + counter election) ----
    __shared__ int slast;
    __syncthreads();
    if (tid == 0) {
        __threadfence();
        int old = atomicAdd(&g_count, 1);
        slast = ((old & 127) == 127) ? 1 : 0;
    }
    __syncthreads();
    if (slast) {
        __threadfence();
        if (tid < 128) {
            sm2[tid]       = g_lse_partial[tid];
            sm2[256 + tid] = (tid < 64) ? g_dotp[tid] : 0.f;
        }
        __syncthreads();
        for (int st = 64; st; st >>= 1) {
            if (tid < st) {
                sm2[tid]       += sm2[tid + st];
                sm2[256 + tid] += sm2[256 + tid + st];
            }
            __syncthreads();
        }
        if (tid == 0) {
            float lsum = sm2[0];                    // full 128-partial sum
            float asum = sm2[256];                  // full 64-partial sum
            float align_mean = asum / (float)NPTS;
            float align = 2.0f - 2.0f * align_mean;
            float unif  = lsum / (float)NPTS;
            out[0] = 4.0f * align + 2.0f * unif;
        }
    }
}

// ---------------- launch ------------------------------------------------------
extern "C" void kernel_launch(void* const* d_in, const int* in_sizes, int n_in,
                              void* d_out, int out_size) {
    const void*  u   = d_in[0];
    const void*  v   = d_in[1];
    const float* emb = (const float*)d_in[2];

    cudaFuncSetAttribute(lse_kernel,
                         cudaFuncAttributeMaxDynamicSharedMemorySize, SM_TOTAL);

    lse_kernel<<<dim3(64, 2, 2), 256, SM_TOTAL>>>(u, v, emb);
    reduce_kernel<<<dim3(64, 2), 1024>>>((float*)d_out);
}

// round 16
// speedup vs baseline: 1.0483x; 1.0483x over previous
#include <cuda_runtime.h>
#include <cuda_fp16.h>
#include <cstdint>

#define NPTS 8192
#define DIM 128
#define SSTRIDE 272                   // f16 tile row stride bytes (136 halves)
#define TILE_BYTES (128 * SSTRIDE)    // 34816

// packed half2 constants: C = 2*log2(e) rounded to f16 = 2.884765625 (0x41C5)
#define SCALE2 0x41C541C5u            // ( C,  C)
#define BIAS2  0xC1C5C1C5u            // (-C, -C)

// ---------------- scratch (device globals; no allocations allowed) ----------
__device__ __half g_src[NPTS * DIM];
__device__ __half g_pos[NPTS * DIM];
__device__ float g_dot[NPTS];
__device__ float g_rowsum[2 * 2 * NPTS];            // [my][z][bi][row]
__device__ float g_cross[2 * 64 * 33 * 2 * 128];    // [my][bj][t][warp_m][row]
__device__ float g_lse_partial[128];                // [my(2)][row-block(64)]
__device__ float g_dotp[64];
__device__ int   g_ready[64];                       // per row-block gather counter (target 4)
__device__ int   g_rdyall;                          // total gather counter (target 256)
__device__ int   g_done;                            // lse completion counter (reset election)
__device__ int   g_count;                           // reduce last-block election counter

// ---------------- PTX helpers ------------------------------------------------
__device__ __forceinline__ uint32_t smem_u32(const void* p) {
    uint32_t a;
    asm("{ .reg .u64 t; cvta.to.shared.u64 t, %1; cvt.u32.u64 %0, t; }"
        : "=r"(a) : "l"(p));
    return a;
}

__device__ __forceinline__ int ld_acquire(const int* p) {
    int v;
    asm volatile("ld.acquire.gpu.global.s32 %0, [%1];" : "=r"(v) : "l"(p));
    return v;
}

__device__ __forceinline__ uint32_t ex2h2(uint32_t a) {
    uint32_t d;
    asm("ex2.approx.f16x2 %0, %1;" : "=r"(d) : "r"(a));
    return d;
}
__device__ __forceinline__ uint32_t hadd2u(uint32_t a, uint32_t b) {
    uint32_t d;
    asm("add.f16x2 %0, %1, %2;" : "=r"(d) : "r"(a), "r"(b));
    return d;
}
__device__ __forceinline__ uint32_t hmul2u(uint32_t a, uint32_t b) {
    uint32_t d;
    asm("mul.f16x2 %0, %1, %2;" : "=r"(d) : "r"(a), "r"(b));
    return d;
}

#define CP_ASYNC16(dst, src) \
    asm volatile("cp.async.cg.shared.global [%0], [%1], 16;" :: "r"(dst), "l"(src) : "memory")
#define CP_COMMIT() asm volatile("cp.async.commit_group;" ::: "memory")
#define CP_WAIT2()  asm volatile("cp.async.wait_group 2;" ::: "memory")
#define CP_WAIT1()  asm volatile("cp.async.wait_group 1;" ::: "memory")
#define CP_WAIT0()  asm volatile("cp.async.wait_group 0;" ::: "memory")

#define LDMATRIX_X4(r0, r1, r2, r3, addr) \
    asm volatile("ldmatrix.sync.aligned.m8n8.x4.shared.b16 {%0,%1,%2,%3}, [%4];" \
                 : "=r"(r0), "=r"(r1), "=r"(r2), "=r"(r3) : "r"(addr))
#define LDMATRIX_X2(r0, r1, addr) \
    asm volatile("ldmatrix.sync.aligned.m8n8.x2.shared.b16 {%0,%1}, [%2];" \
                 : "=r"(r0), "=r"(r1) : "r"(addr))

// f16 x f16 -> f16 accumulate: D/C are 2 x .f16x2 registers.
#define MMA16816H(c0, c1, a0, a1, a2, a3, b0, b1) \
    asm volatile("mma.sync.aligned.m16n8k16.row.col.f16.f16.f16.f16 " \
                 "{%0,%1}, {%2,%3,%4,%5}, {%6,%7}, {%0,%1};" \
                 : "+r"(c0), "+r"(c1) \
                 : "r"(a0), "r"(a1), "r"(a2), "r"(a3), "r"(b0), "r"(b1))

// ---------------- fused gather + HMMA-f16 Gram + exp sums --------------------
// grid (64, 2, 2): x = row-block bi, y = matrix, z = t-range half.
// Phase 1: CTA (bi,my,zz) gathers rows bi*128 + (my*2+zz)*32 + [0,32).
//   Readiness: g_ready[bi] (target 4) + g_rdyall (target 256).
// Phase 2: tournament tiles (bi, (bi+t)%64), t in z's half of [0,NT).
//   Tile waits use a register fast path: once tid0 observes g_rdyall>=256 it
//   never touches memory again (steady-state wait = branch + bar.sync).
// All 256 CTAs are wave-1 resident (2 CTAs/SM) so the flags cannot deadlock.
#define SM_A  0
#define SM_B0 TILE_BYTES
#define SM_B1 (2 * TILE_BYTES)
#define SM_TOTAL (3 * TILE_BYTES)

__device__ __forceinline__ void load_tile(uint32_t sdst, const uint4* eg,
                                          int row0, int tid) {
    #pragma unroll
    for (int it = 0; it < 8; it++) {
        int idx = tid + it * 256;
        int r = idx >> 4, c = idx & 15;
        CP_ASYNC16(sdst + r * SSTRIDE + c * 16, eg + (row0 + r) * 16 + c);
    }
}

__global__ void __launch_bounds__(256, 2) lse_kernel(
        const void* __restrict__ u_raw, const void* __restrict__ v_raw,
        const float* __restrict__ emb) {
    extern __shared__ char smem[];
    const uint32_t sbase = smem_u32(smem);
    const int tid = threadIdx.x;
    const int lane = tid & 31;
    const int warp = tid >> 5;            // 0..7
    const int warp_m = warp >> 2;         // 0..1 -> 64 rows each
    const int warp_n = warp & 3;          // 0..3 -> 32 cols each
    const int m_base = warp_m * 64;
    const int n_base = warp_n * 32;
    const int bi = blockIdx.x;
    const int my = blockIdx.y;
    const int zz = blockIdx.z;
    const int NT = 32 + (bi < 32 ? 1 : 0);
    const int t0 = zz * 16;
    const int tEnd = zz == 0 ? 16 : NT;

    // ---------------- phase 1: gather 32 rows (both matrices) ----------------
    {
        const int* u32 = (const int*)u_raw;
        int nz = u32[2 * lane + 1];
        #pragma unroll
        for (int off = 16; off; off >>= 1)
            nz |= __shfl_xor_sync(0xffffffffu, nz, off);
        const bool is64 = (nz == 0);

        const int rbase = bi * 128 + (my * 2 + zz) * 32;
        #pragma unroll
        for (int it = 0; it < 4; it++) {
            int row = rbase + it * 8 + warp;

            long long ui, vi;
            if (is64) {
                ui = ((const long long*)u_raw)[row];
                vi = ((const long long*)v_raw)[row];
            } else {
                ui = ((const int*)u_raw)[row];
                vi = ((const int*)v_raw)[row];
            }

            float4 xu = ((const float4*)(emb + ui * DIM))[lane];
            float4 xv = ((const float4*)(emb + vi * DIM))[lane];

            float su2 = xu.x * xu.x + xu.y * xu.y + xu.z * xu.z + xu.w * xu.w;
            float sv2 = xv.x * xv.x + xv.y * xv.y + xv.z * xv.z + xv.w * xv.w;
            #pragma unroll
            for (int off = 16; off; off >>= 1) {
                su2 += __shfl_xor_sync(0xffffffffu, su2, off);
                sv2 += __shfl_xor_sync(0xffffffffu, sv2, off);
            }

            float ru = 1.0f / fmaxf(sqrtf(su2), 1e-12f);
            float rv = 1.0f / fmaxf(sqrtf(sv2), 1e-12f);
            float sux = xu.x * ru, suy = xu.y * ru, suz = xu.z * ru, suw = xu.w * ru;
            float svx = xv.x * rv, svy = xv.y * rv, svz = xv.z * rv, svw = xv.w * rv;

            __half2 u01 = __floats2half2_rn(sux, suy);
            __half2 u23 = __floats2half2_rn(suz, suw);
            __half2 v01 = __floats2half2_rn(svx, svy);
            __half2 v23 = __floats2half2_rn(svz, svw);
            *(uint2*)&g_src[row * DIM + lane * 4] =
                make_uint2(*(uint32_t*)&u01, *(uint32_t*)&u23);
            *(uint2*)&g_pos[row * DIM + lane * 4] =
                make_uint2(*(uint32_t*)&v01, *(uint32_t*)&v23);

            float dp = sux * svx + suy * svy + suz * svz + suw * svw;
            #pragma unroll
            for (int off = 16; off; off >>= 1)
                dp += __shfl_xor_sync(0xffffffffu, dp, off);
            if (lane == 0) g_dot[row] = dp;
        }
        __threadfence();                   // publish rows before flagging
        __syncthreads();
        if (tid == 0) {
            atomicAdd(&g_ready[bi], 1);
            atomicAdd(&g_rdyall, 1);
        }
    }

    // ---------------- phase 2: tournament MMA + exp sums ----------------
    const __half* e = (my == 0) ? g_src : g_pos;
    const uint4* eg = (const uint4*)e;

    bool allrdy = false;                   // tid0-only register fast path
    #define WAIT_BLOCK(b) do { \
        if (tid == 0 && !allrdy) { \
            if (ld_acquire(&g_rdyall) >= 256) allrdy = true; \
            else { while (ld_acquire(&g_ready[(b)]) < 4) { } } \
        } \
        __syncthreads(); \
    } while (0)

    // prologue: A alone in group0, B(t0) group1, B(t0+1) group2
    WAIT_BLOCK(bi);
    load_tile(sbase + SM_A, eg, bi * 128, tid);
    CP_COMMIT();
    WAIT_BLOCK((bi + t0) & 63);
    load_tile(sbase + SM_B0, eg, ((bi + t0) & 63) * 128, tid);
    CP_COMMIT();
    WAIT_BLOCK((bi + t0 + 1) & 63);
    load_tile(sbase + SM_B1, eg, ((bi + t0 + 1) & 63) * 128, tid);
    CP_COMMIT();

    // A landed -> scale it by C in place (pad bytes scaled too: never read)
    CP_WAIT2();
    {
        uint32_t* aw = (uint32_t*)smem;
        #pragma unroll
        for (int i = tid; i < TILE_BYTES / 4; i += 256)
            aw[i] = hmul2u(aw[i], SCALE2);
    }

    const int l15 = lane & 15;
    const uint32_t aAddr0 = sbase + SM_A +
        (uint32_t)(m_base + l15) * SSTRIDE + (uint32_t)(lane >> 4) * 16;
    const uint32_t bOff0 =
        (uint32_t)(n_base + (l15 & 7)) * SSTRIDE + (uint32_t)(l15 >> 3) * 16;

    uint32_t acc[4][4][2];                // f16x2 accumulators, bias-initialized
    #pragma unroll
    for (int mt = 0; mt < 4; mt++)
        #pragma unroll
        for (int nt = 0; nt < 4; nt++) { acc[mt][nt][0] = BIAS2; acc[mt][nt][1] = BIAS2; }

    float rowsum[8];
    #pragma unroll
    for (int j = 0; j < 8; j++) rowsum[j] = 0.f;

    for (int t = t0; t < tEnd; t++) {
        if (t < tEnd - 1) { CP_WAIT1(); } else { CP_WAIT0(); }
        __syncthreads();                  // covers A-scale stores + B_t arrival

        const uint32_t bAddr0 = sbase + ((t & 1) ? SM_B1 : SM_B0) + bOff0;

        #pragma unroll
        for (int k = 0; k < 8; k++) {
            uint32_t b[4][2];
            #pragma unroll
            for (int nt = 0; nt < 4; nt++)
                LDMATRIX_X2(b[nt][0], b[nt][1],
                            bAddr0 + nt * (8 * SSTRIDE) + k * 32);
            #pragma unroll
            for (int mt = 0; mt < 4; mt++) {
                uint32_t a0, a1, a2, a3;
                LDMATRIX_X4(a0, a1, a2, a3,
                            aAddr0 + mt * (16 * SSTRIDE) + k * 32);
                #pragma unroll
                for (int nt = 0; nt < 4; nt++)
                    MMA16816H(acc[mt][nt][0], acc[mt][nt][1],
                              a0, a1, a2, a3, b[nt][0], b[nt][1]);
            }
        }

        __syncthreads();            // all warps done reading this B buffer
        if (t + 2 < tEnd) {
            WAIT_BLOCK((bi + t + 2) & 63);
            load_tile(sbase + ((t & 1) ? SM_B1 : SM_B0), eg,
                      ((bi + t + 2) & 63) * 128, tid);
            CP_COMMIT();
        }

        // epilogue: acc already = C*d - C; ev = ex2(acc)
        uint32_t cs2[4];
        #pragma unroll
        for (int nt = 0; nt < 4; nt++) cs2[nt] = 0u;

        #pragma unroll
        for (int mt = 0; mt < 4; mt++) {
            uint32_t sr01 = 0u, sr23 = 0u;      // half2 row partials
            #pragma unroll
            for (int nt = 0; nt < 4; nt++) {
                uint32_t h01 = ex2h2(acc[mt][nt][0]);   // row r  : cols c,c+1
                uint32_t h23 = ex2h2(acc[mt][nt][1]);   // row r+8: cols c,c+1
                sr01 = hadd2u(sr01, h01);
                sr23 = hadd2u(sr23, h23);
                cs2[nt] = hadd2u(cs2[nt], hadd2u(h01, h23));
                acc[mt][nt][0] = BIAS2; acc[mt][nt][1] = BIAS2;
            }
            float2 fr01 = __half22float2(*(__half2*)&sr01);
            float2 fr23 = __half22float2(*(__half2*)&sr23);
            rowsum[mt * 2]     += fr01.x + fr01.y;
            rowsum[mt * 2 + 1] += fr23.x + fr23.y;
        }

        if (t != 0) {
            // col sums: xor-reduce half2 over the 8 row-groups, store f32
            #pragma unroll
            for (int nt = 0; nt < 4; nt++) {
                uint32_t c = cs2[nt];
                c = hadd2u(c, __shfl_xor_sync(0xffffffffu, c, 4));
                c = hadd2u(c, __shfl_xor_sync(0xffffffffu, c, 8));
                c = hadd2u(c, __shfl_xor_sync(0xffffffffu, c, 16));
                cs2[nt] = c;
            }
            if (lane < 4) {
                int bj = (bi + t) & 63;
                float2* dst = (float2*)&g_cross[
                    ((((my * 64 + bj) * 33 + t) * 2 + warp_m) * 128)
                    + n_base + lane * 2];
                #pragma unroll
                for (int nt = 0; nt < 4; nt++) {
                    float2 f = __half22float2(*(__half2*)&cs2[nt]);
                    dst[nt * 4] = f;
                }
            }
        }
    }
    #undef WAIT_BLOCK

    // ---- own row sums: quad lanes share rows ----
    #pragma unroll
    for (int j = 0; j < 8; j++) {
        rowsum[j] += __shfl_xor_sync(0xffffffffu, rowsum[j], 1);
        rowsum[j] += __shfl_xor_sync(0xffffffffu, rowsum[j], 2);
    }

    float* red = (float*)smem;            // reuse A region
    __syncthreads();
    if ((lane & 3) == 0) {
        #pragma unroll
        for (int mt = 0; mt < 4; mt++) {
            int row = m_base + mt * 16 + (lane >> 2);
            red[warp_n * 128 + row]     = rowsum[mt * 2];
            red[warp_n * 128 + row + 8] = rowsum[mt * 2 + 1];
        }
    }
    __syncthreads();
    if (tid < 128) {
        float s = red[tid] + red[128 + tid] + red[256 + tid] + red[384 + tid];
        g_rowsum[((my * 2 + zz) * 64 + bi) * 128 + tid] = s;
    }

    // ---- replay-safe flag reset: last CTA of this launch zeroes flags ----
    __syncthreads();
    if (tid == 0) {
        __threadfence();
        int old = atomicAdd(&g_done, 1);
        if ((old & 255) == 255) {
            #pragma unroll
            for (int i = 0; i < 64; i++) g_ready[i] = 0;
            g_rdyall = 0;
            __threadfence();
        }
    }
}

// ------- per-row combine + log + block partial + fenced last-block finalize --
__global__ void __launch_bounds__(1024) reduce_kernel(float* __restrict__ out) {
    const int bi = blockIdx.x;
    const int my = blockIdx.y;
    const int tid = threadIdx.x;         // 0..1023
    const int r = tid & 127;
    const int q = tid >> 7;              // segment 0..7

    const float* cr = &g_cross[(my * 64 + bi) * 33 * 2 * 128 + r];
    float s = 0.f;
    if (q == 0) {
        s += g_rowsum[((my * 2 + 0) * 64 + bi) * 128 + r];
        s += g_rowsum[((my * 2 + 1) * 64 + bi) * 128 + r];
        #pragma unroll
        for (int t = 1; t <= 4; t++)  s += cr[t * 256] + cr[t * 256 + 128];
    } else if (q < 7) {
        const int tb = q * 4;            // q=1 -> 5..8, ..., q=6 -> 25..28
        #pragma unroll
        for (int t = 1; t <= 4; t++)
            s += cr[(tb + t) * 256] + cr[(tb + t) * 256 + 128];
    } else {
        const int tMax = (bi >= 32) ? 32 : 31;
        for (int t = 29; t <= tMax; t++) s += cr[t * 256] + cr[t * 256 + 128];
    }

    __shared__ float sm2[1024];
    sm2[tid] = s;
    __syncthreads();
    if (q == 0) {
        float v = sm2[r];
        #pragma unroll
        for (int j = 1; j < 8; j++) v += sm2[r + 128 * j];
        sm2[r] = logf(v);
    }
    __syncthreads();
    for (int st = 64; st; st >>= 1) {
        if (tid < st) sm2[tid] += sm2[tid + st];
        __syncthreads();
    }
    if (tid == 0) g_lse_partial[my * 64 + bi] = sm2[0];

    if (my == 0) {
        sm2[tid] = (tid < 128) ? g_dot[bi * 128 + tid] : 0.f;
        __syncthreads();
        for (int st = 64; st; st >>= 1) {
            if (tid < st) sm2[tid] += sm2[tid + st];
            __syncthreads();
        }
        if (tid == 0) g_dotp[bi] = sm2[0];
    }

    // ---- last-of-128-blocks finalize (threadfence + counter election) ----
    __shared__ int slast;
    __syncthreads();
    if (tid == 0) {
        __threadfence();
        int old = atomicAdd(&g_count, 1);
        slast = ((old & 127) == 127) ? 1 : 0;
    }
    __syncthreads();
    if (slast) {
        __threadfence();
        if (tid < 128) {
            sm2[tid]       = g_lse_partial[tid];
            sm2[256 + tid] = (tid < 64) ? g_dotp[tid] : 0.f;
        }
        __syncthreads();
        for (int st = 64; st; st >>= 1) {
            if (tid < st) {
                sm2[tid]       += sm2[tid + st];
                sm2[256 + tid] += sm2[256 + tid + st];
            }
            __syncthreads();
        }
        if (tid == 0) {
            float lsum = sm2[0];                    // full 128-partial sum
            float asum = sm2[256];                  // full 64-partial sum
            float align_mean = asum / (float)NPTS;
            float align = 2.0f - 2.0f * align_mean;
            float unif  = lsum / (float)NPTS;
            out[0] = 4.0f * align + 2.0f * unif;
        }
    }
}

// ---------------- launch ------------------------------------------------------
extern "C" void kernel_launch(void* const* d_in, const int* in_sizes, int n_in,
                              void* d_out, int out_size) {
    const void*  u   = d_in[0];
    const void*  v   = d_in[1];
    const float* emb = (const float*)d_in[2];

    cudaFuncSetAttribute(lse_kernel,
                         cudaFuncAttributeMaxDynamicSharedMemorySize, SM_TOTAL);

    lse_kernel<<<dim3(64, 2, 2), 256, SM_TOTAL>>>(u, v, emb);
    reduce_kernel<<<dim3(64, 2), 1024>>>((float*)d_out);
}

// round 17
// speedup vs baseline: 1.1666x; 1.1128x over previous
#include <cuda_runtime.h>
#include <cuda_fp16.h>
#include <cstdint>

#define NPTS 8192
#define DIM 128
#define SSTRIDE 272                   // f16 tile row stride bytes (136 halves)
#define TILE_BYTES (128 * SSTRIDE)    // 34816

// packed half2 constants: C = 2*log2(e) rounded to f16 = 2.884765625 (0x41C5)
#define SCALE2 0x41C541C5u            // ( C,  C)
#define BIAS2  0xC1C5C1C5u            // (-C, -C)

// ---------------- scratch (device globals; no allocations allowed) ----------
__device__ __half g_src[NPTS * DIM];
__device__ __half g_pos[NPTS * DIM];
__device__ float g_dot[NPTS];
__device__ float g_rowsum[2 * 2 * NPTS];            // [my][z][bi][row]
__device__ uint32_t g_crossh[2 * 64 * 33 * 2 * 64]; // [my][bj][t][warp_m][col pair] half2
__device__ float g_lse_partial[128];                // [my(2)][row-block(64)]
__device__ float g_dotp[64];
__device__ int   g_count;                           // reduce last-block election counter

// ---------------- PTX helpers ------------------------------------------------
__device__ __forceinline__ uint32_t smem_u32(const void* p) {
    uint32_t a;
    asm("{ .reg .u64 t; cvta.to.shared.u64 t, %1; cvt.u32.u64 %0, t; }"
        : "=r"(a) : "l"(p));
    return a;
}

__device__ __forceinline__ uint32_t ex2h2(uint32_t a) {
    uint32_t d;
    asm("ex2.approx.f16x2 %0, %1;" : "=r"(d) : "r"(a));
    return d;
}
__device__ __forceinline__ uint32_t hadd2u(uint32_t a, uint32_t b) {
    uint32_t d;
    asm("add.f16x2 %0, %1, %2;" : "=r"(d) : "r"(a), "r"(b));
    return d;
}
__device__ __forceinline__ uint32_t hmul2u(uint32_t a, uint32_t b) {
    uint32_t d;
    asm("mul.f16x2 %0, %1, %2;" : "=r"(d) : "r"(a), "r"(b));
    return d;
}

#define CP_ASYNC16(dst, src) \
    asm volatile("cp.async.cg.shared.global [%0], [%1], 16;" :: "r"(dst), "l"(src) : "memory")
#define CP_COMMIT() asm volatile("cp.async.commit_group;" ::: "memory")
#define CP_WAIT2()  asm volatile("cp.async.wait_group 2;" ::: "memory")
#define CP_WAIT1()  asm volatile("cp.async.wait_group 1;" ::: "memory")
#define CP_WAIT0()  asm volatile("cp.async.wait_group 0;" ::: "memory")

#define LDMATRIX_X4(r0, r1, r2, r3, addr) \
    asm volatile("ldmatrix.sync.aligned.m8n8.x4.shared.b16 {%0,%1,%2,%3}, [%4];" \
                 : "=r"(r0), "=r"(r1), "=r"(r2), "=r"(r3) : "r"(addr))
#define LDMATRIX_X2(r0, r1, addr) \
    asm volatile("ldmatrix.sync.aligned.m8n8.x2.shared.b16 {%0,%1}, [%2];" \
                 : "=r"(r0), "=r"(r1) : "r"(addr))

// f16 x f16 -> f16 accumulate: D/C are 2 x .f16x2 registers.
#define MMA16816H(c0, c1, a0, a1, a2, a3, b0, b1) \
    asm volatile("mma.sync.aligned.m16n8k16.row.col.f16.f16.f16.f16 " \
                 "{%0,%1}, {%2,%3,%4,%5}, {%6,%7}, {%0,%1};" \
                 : "+r"(c0), "+r"(c1) \
                 : "r"(a0), "r"(a1), "r"(a2), "r"(a3), "r"(b0), "r"(b1))

// ---------------- gather + L2 normalize + align dot (+f16 store) -------------
// grid 1024 x block 256. Warp-per-row. Lane l owns dims [4l, 4l+4).
// int64-vs-int32 index detection per-warp (odd 32-bit lanes of an int64 array
// of values < 2^31 are all zero).
__global__ void __launch_bounds__(256) gather_norm_kernel(
        const void* __restrict__ u_raw, const void* __restrict__ v_raw,
        const float* __restrict__ emb) {
    const int lane = threadIdx.x & 31;
    const int warp = threadIdx.x >> 5;
    const int row  = blockIdx.x * 8 + warp;

    const int* u32 = (const int*)u_raw;
    int nz = u32[2 * lane + 1];
    #pragma unroll
    for (int off = 16; off; off >>= 1)
        nz |= __shfl_xor_sync(0xffffffffu, nz, off);
    const bool is64 = (nz == 0);

    long long ui, vi;
    if (is64) {
        ui = ((const long long*)u_raw)[row];
        vi = ((const long long*)v_raw)[row];
    } else {
        ui = ((const int*)u_raw)[row];
        vi = ((const int*)v_raw)[row];
    }

    float4 xu = ((const float4*)(emb + ui * DIM))[lane];
    float4 xv = ((const float4*)(emb + vi * DIM))[lane];

    float su2 = xu.x * xu.x + xu.y * xu.y + xu.z * xu.z + xu.w * xu.w;
    float sv2 = xv.x * xv.x + xv.y * xv.y + xv.z * xv.z + xv.w * xv.w;
    #pragma unroll
    for (int off = 16; off; off >>= 1) {
        su2 += __shfl_xor_sync(0xffffffffu, su2, off);
        sv2 += __shfl_xor_sync(0xffffffffu, sv2, off);
    }

    float ru = 1.0f / fmaxf(sqrtf(su2), 1e-12f);
    float rv = 1.0f / fmaxf(sqrtf(sv2), 1e-12f);
    float sux = xu.x * ru, suy = xu.y * ru, suz = xu.z * ru, suw = xu.w * ru;
    float svx = xv.x * rv, svy = xv.y * rv, svz = xv.z * rv, svw = xv.w * rv;

    __half2 u01 = __floats2half2_rn(sux, suy);
    __half2 u23 = __floats2half2_rn(suz, suw);
    __half2 v01 = __floats2half2_rn(svx, svy);
    __half2 v23 = __floats2half2_rn(svz, svw);
    *(uint2*)&g_src[row * DIM + lane * 4] =
        make_uint2(*(uint32_t*)&u01, *(uint32_t*)&u23);
    *(uint2*)&g_pos[row * DIM + lane * 4] =
        make_uint2(*(uint32_t*)&v01, *(uint32_t*)&v23);

    float dp = sux * svx + suy * svy + suz * svz + suw * svw;
    #pragma unroll
    for (int off = 16; off; off >>= 1)
        dp += __shfl_xor_sync(0xffffffffu, dp, off);
    if (lane == 0) g_dot[row] = dp;
}

// ---------------- fused HMMA-f16 Gram (symmetric half) + exp sums ------------
// grid (64, 2, 2): x = row-block bi, y = matrix, z = t-range half.
// Tournament: tiles (bi, (bi+t)%64) for t in z's half of [0,NT), NT=32(+1 bi<32).
// A-tile pre-scaled by C in smem; acc initialized to -C -> acc = C*d - C and
// the epilogue is just ex2.f16x2 + HADD2. Col-sum partials stored as half2.
#define SM_A  0
#define SM_B0 TILE_BYTES
#define SM_B1 (2 * TILE_BYTES)
#define SM_TOTAL (3 * TILE_BYTES)

__device__ __forceinline__ void load_tile(uint32_t sdst, const uint4* eg,
                                          int row0, int tid) {
    #pragma unroll
    for (int it = 0; it < 8; it++) {
        int idx = tid + it * 256;
        int r = idx >> 4, c = idx & 15;
        CP_ASYNC16(sdst + r * SSTRIDE + c * 16, eg + (row0 + r) * 16 + c);
    }
}

__global__ void __launch_bounds__(256, 2) lse_kernel() {
    extern __shared__ char smem[];
    const uint32_t sbase = smem_u32(smem);
    const int tid = threadIdx.x;
    const int lane = tid & 31;
    const int warp_m = (tid >> 5) >> 2;   // 0..1 -> 64 rows each
    const int warp_n = (tid >> 5) & 3;    // 0..3 -> 32 cols each
    const int m_base = warp_m * 64;
    const int n_base = warp_n * 32;
    const int bi = blockIdx.x;
    const int my = blockIdx.y;
    const int zz = blockIdx.z;
    const int NT = 32 + (bi < 32 ? 1 : 0);
    const int t0 = zz * 16;
    const int tEnd = zz == 0 ? 16 : NT;

    const __half* e = (my == 0) ? g_src : g_pos;
    const uint4* eg = (const uint4*)e;

    // prologue: A alone in group0, B(t0) group1, B(t0+1) group2
    load_tile(sbase + SM_A, eg, bi * 128, tid);
    CP_COMMIT();
    load_tile(sbase + SM_B0, eg, ((bi + t0) & 63) * 128, tid);
    CP_COMMIT();
    load_tile(sbase + SM_B1, eg, ((bi + t0 + 1) & 63) * 128, tid);
    CP_COMMIT();

    // A landed -> scale it by C in place (pad bytes scaled too: never read)
    CP_WAIT2();
    {
        uint32_t* aw = (uint32_t*)smem;
        #pragma unroll
        for (int i = tid; i < TILE_BYTES / 4; i += 256)
            aw[i] = hmul2u(aw[i], SCALE2);
    }

    const int l15 = lane & 15;
    const uint32_t aAddr0 = sbase + SM_A +
        (uint32_t)(m_base + l15) * SSTRIDE + (uint32_t)(lane >> 4) * 16;
    const uint32_t bOff0 =
        (uint32_t)(n_base + (l15 & 7)) * SSTRIDE + (uint32_t)(l15 >> 3) * 16;

    uint32_t acc[4][4][2];                // f16x2 accumulators, bias-initialized
    #pragma unroll
    for (int mt = 0; mt < 4; mt++)
        #pragma unroll
        for (int nt = 0; nt < 4; nt++) { acc[mt][nt][0] = BIAS2; acc[mt][nt][1] = BIAS2; }

    float rowsum[8];
    #pragma unroll
    for (int j = 0; j < 8; j++) rowsum[j] = 0.f;

    for (int t = t0; t < tEnd; t++) {
        if (t < tEnd - 1) { CP_WAIT1(); } else { CP_WAIT0(); }
        __syncthreads();                  // covers A-scale stores + B_t arrival

        const uint32_t bAddr0 = sbase + ((t & 1) ? SM_B1 : SM_B0) + bOff0;

        #pragma unroll
        for (int k = 0; k < 8; k++) {
            uint32_t b[4][2];
            #pragma unroll
            for (int nt = 0; nt < 4; nt++)
                LDMATRIX_X2(b[nt][0], b[nt][1],
                            bAddr0 + nt * (8 * SSTRIDE) + k * 32);
            #pragma unroll
            for (int mt = 0; mt < 4; mt++) {
                uint32_t a0, a1, a2, a3;
                LDMATRIX_X4(a0, a1, a2, a3,
                            aAddr0 + mt * (16 * SSTRIDE) + k * 32);
                #pragma unroll
                for (int nt = 0; nt < 4; nt++)
                    MMA16816H(acc[mt][nt][0], acc[mt][nt][1],
                              a0, a1, a2, a3, b[nt][0], b[nt][1]);
            }
        }

        __syncthreads();            // all warps done reading this B buffer
        if (t + 2 < tEnd) {
            load_tile(sbase + ((t & 1) ? SM_B1 : SM_B0), eg,
                      ((bi + t + 2) & 63) * 128, tid);
            CP_COMMIT();
        }

        // epilogue: acc already = C*d - C; ev = ex2(acc)
        uint32_t cs2[4];
        #pragma unroll
        for (int nt = 0; nt < 4; nt++) cs2[nt] = 0u;

        #pragma unroll
        for (int mt = 0; mt < 4; mt++) {
            uint32_t sr01 = 0u, sr23 = 0u;      // half2 row partials
            #pragma unroll
            for (int nt = 0; nt < 4; nt++) {
                uint32_t h01 = ex2h2(acc[mt][nt][0]);   // row r  : cols c,c+1
                uint32_t h23 = ex2h2(acc[mt][nt][1]);   // row r+8: cols c,c+1
                sr01 = hadd2u(sr01, h01);
                sr23 = hadd2u(sr23, h23);
                cs2[nt] = hadd2u(cs2[nt], hadd2u(h01, h23));
                acc[mt][nt][0] = BIAS2; acc[mt][nt][1] = BIAS2;
            }
            float2 fr01 = __half22float2(*(__half2*)&sr01);
            float2 fr23 = __half22float2(*(__half2*)&sr23);
            rowsum[mt * 2]     += fr01.x + fr01.y;
            rowsum[mt * 2 + 1] += fr23.x + fr23.y;
        }

        if (t != 0) {
            // col sums: xor-reduce half2 over the 8 row-groups, store PACKED
            #pragma unroll
            for (int nt = 0; nt < 4; nt++) {
                uint32_t c = cs2[nt];
                c = hadd2u(c, __shfl_xor_sync(0xffffffffu, c, 4));
                c = hadd2u(c, __shfl_xor_sync(0xffffffffu, c, 8));
                c = hadd2u(c, __shfl_xor_sync(0xffffffffu, c, 16));
                cs2[nt] = c;
            }
            if (lane < 4) {
                int bj = (bi + t) & 63;
                // word index: cols (n_base + nt*8 + lane*2) / 2
                uint32_t* dst = &g_crossh[
                    ((((my * 64 + bj) * 33 + t) * 2 + warp_m) * 64)
                    + (n_base >> 1) + lane];
                #pragma unroll
                for (int nt = 0; nt < 4; nt++)
                    dst[nt * 4] = cs2[nt];
            }
        }
    }

    // ---- own row sums: quad lanes share rows ----
    #pragma unroll
    for (int j = 0; j < 8; j++) {
        rowsum[j] += __shfl_xor_sync(0xffffffffu, rowsum[j], 1);
        rowsum[j] += __shfl_xor_sync(0xffffffffu, rowsum[j], 2);
    }

    float* red = (float*)smem;            // reuse A region
    __syncthreads();
    if ((lane & 3) == 0) {
        #pragma unroll
        for (int mt = 0; mt < 4; mt++) {
            int row = m_base + mt * 16 + (lane >> 2);
            red[warp_n * 128 + row]     = rowsum[mt * 2];
            red[warp_n * 128 + row + 8] = rowsum[mt * 2 + 1];
        }
    }
    __syncthreads();
    if (tid < 128) {
        float s = red[tid] + red[128 + tid] + red[256 + tid] + red[384 + tid];
        g_rowsum[((my * 2 + zz) * 64 + bi) * 128 + tid] = s;
    }
}

// ------- per-row combine + log + block partial + fenced last-block finalize --
// 512 threads; 4 t-segments per row; packed half2 cross loads.
__global__ void __launch_bounds__(512) reduce_kernel(float* __restrict__ out) {
    const int bi = blockIdx.x;
    const int my = blockIdx.y;
    const int tid = threadIdx.x;         // 0..511
    const int r = tid & 127;
    const int q = tid >> 7;              // segment 0..3

    // word pointer for row r: slot (t, wm) lives at t*128 + wm*64 words
    const uint32_t* cr = &g_crossh[(my * 64 + bi) * 33 * 2 * 64 + (r >> 1)];
    const int hi = r & 1;

    float s = 0.f;
    #define CROSS_AT(t, wm) __half2float(((const __half*)&cr[(t) * 128 + (wm) * 64])[hi])
    if (q == 0) {
        s += g_rowsum[((my * 2 + 0) * 64 + bi) * 128 + r];
        s += g_rowsum[((my * 2 + 1) * 64 + bi) * 128 + r];
        #pragma unroll
        for (int t = 1; t <= 8; t++)  s += CROSS_AT(t, 0) + CROSS_AT(t, 1);
    } else if (q == 1) {
        #pragma unroll
        for (int t = 9; t <= 16; t++) s += CROSS_AT(t, 0) + CROSS_AT(t, 1);
    } else if (q == 2) {
        #pragma unroll
        for (int t = 17; t <= 24; t++) s += CROSS_AT(t, 0) + CROSS_AT(t, 1);
    } else {
        const int tMax = (bi >= 32) ? 32 : 31;
        for (int t = 25; t <= tMax; t++) s += CROSS_AT(t, 0) + CROSS_AT(t, 1);
    }
    #undef CROSS_AT

    __shared__ float sm2[512];
    sm2[tid] = s;
    __syncthreads();
    if (q == 0)
        sm2[r] = logf(sm2[r] + sm2[r + 128] + sm2[r + 256] + sm2[r + 384]);
    __syncthreads();
    // tree over sm2[0..127]
    for (int st = 64; st; st >>= 1) {
        if (tid < st) sm2[tid] += sm2[tid + st];
        __syncthreads();
    }
    if (tid == 0) g_lse_partial[my * 64 + bi] = sm2[0];

    if (my == 0) {
        sm2[tid] = (tid < 128) ? g_dot[bi * 128 + tid] : 0.f;
        __syncthreads();
        for (int st = 64; st; st >>= 1) {
            if (tid < st) sm2[tid] += sm2[tid + st];
            __syncthreads();
        }
        if (tid == 0) g_dotp[bi] = sm2[0];
    }

    // ---- last-of-128-blocks finalize (threadfence + counter election) ----
    __shared__ int slast;
    __syncthreads();
    if (tid == 0) {
        __threadfence();
        int old = atomicAdd(&g_count, 1);
        slast = ((old & 127) == 127) ? 1 : 0;
    }
    __syncthreads();
    if (slast) {
        __threadfence();
        if (tid < 128) {
            sm2[tid]       = g_lse_partial[tid];
            sm2[256 + tid] = (tid < 64) ? g_dotp[tid] : 0.f;
        }
        __syncthreads();
        for (int st = 64; st; st >>= 1) {
            if (tid < st) {
                sm2[tid]       += sm2[tid + st];
                sm2[256 + tid] += sm2[256 + tid + st];
            }
            __syncthreads();
        }
        if (tid == 0) {
            float lsum = sm2[0];                    // full 128-partial sum
            float asum = sm2[256];                  // full 64-partial sum
            float align_mean = asum / (float)NPTS;
            float align = 2.0f - 2.0f * align_mean;
            float unif  = lsum / (float)NPTS;
            out[0] = 4.0f * align + 2.0f * unif;
        }
    }
}

// ---------------- launch ------------------------------------------------------
extern "C" void kernel_launch(void* const* d_in, const int* in_sizes, int n_in,
                              void* d_out, int out_size) {
    const void*  u   = d_in[0];
    const void*  v   = d_in[1];
    const float* emb = (const float*)d_in[2];

    cudaFuncSetAttribute(lse_kernel,
                         cudaFuncAttributeMaxDynamicSharedMemorySize, SM_TOTAL);

    gather_norm_kernel<<<1024, 256>>>(u, v, emb);
    lse_kernel<<<dim3(64, 2, 2), 256, SM_TOTAL>>>();
    reduce_kernel<<<dim3(64, 2), 512>>>((float*)d_out);
}